// round 6
// baseline (speedup 1.0000x reference)
#include <cuda_runtime.h>

#define TILE_R 128
#define DIMS   128
#define MSLOTS 64
#define NTHREADS 512

// shared memory layout (floats):
//  xs  [128][132]  x tile, padded
//  ms  [64][128]   memory row-major
//  msT [128][68]   memory transposed (dim-major), padded
//  sims[128][65]   similarity / exp values, padded
//  gw  [128]       gate weights
//  grow[128]       sigmoid gate per row
//  rinv[128]       1/sum(exp) per row
#define XS_PITCH   132
#define MST_PITCH  68
#define SIMS_PITCH 65
#define SMEM_FLOATS (TILE_R*XS_PITCH + MSLOTS*DIMS + DIMS*MST_PITCH + TILE_R*SIMS_PITCH + 3*TILE_R)

typedef unsigned long long ull;

static __device__ __forceinline__ ull pk2(float lo, float hi) {
    ull r; asm("mov.b64 %0, {%1, %2};" : "=l"(r) : "f"(lo), "f"(hi)); return r;
}
static __device__ __forceinline__ ull fma2(ull a, ull b, ull c) {
    ull d; asm("fma.rn.f32x2 %0, %1, %2, %3;" : "=l"(d) : "l"(a), "l"(b), "l"(c)); return d;
}
static __device__ __forceinline__ float2 upk(ull v) {
    float2 f; asm("mov.b64 {%0, %1}, %2;" : "=f"(f.x), "=f"(f.y) : "l"(v)); return f;
}

__global__ __launch_bounds__(NTHREADS, 1)
void gated_memory_kernel(const float* __restrict__ x,
                         const float* __restrict__ mem,
                         const float* __restrict__ gate_w,
                         const float* __restrict__ gate_b,
                         float* __restrict__ out,
                         int n)
{
    extern __shared__ float sm[];
    float* xs   = sm;                            // 128*132
    float* ms   = xs  + TILE_R * XS_PITCH;       // 64*128
    float* msT  = ms  + MSLOTS * DIMS;           // 128*68
    float* sims = msT + DIMS * MST_PITCH;        // 128*65
    float* gw   = sims + TILE_R * SIMS_PITCH;    // 128
    float* grow = gw + DIMS;                     // 128
    float* rinv = grow + TILE_R;                 // 128

    const int tid = threadIdx.x;
    const int tx  = tid & 15;    // 0..15
    const int ty  = tid >> 4;    // 0..31
    const int row0 = blockIdx.x * TILE_R;

    // ---- load memory into ms (row-major) and msT (transposed, padded) ----
    #pragma unroll
    for (int it = 0; it < (MSLOTS * DIMS) / NTHREADS; ++it) {  // 16 iters
        int idx = it * NTHREADS + tid;
        int s = idx >> 7;         // slot
        int d = idx & 127;        // dim
        float v = mem[idx];
        ms[s * DIMS + d] = v;
        msT[d * MST_PITCH + s] = v;
    }
    if (tid < DIMS) gw[tid] = gate_w[tid];

    // ---- load x tile (float4, coalesced), zero-fill OOB rows ----
    {
        const float4* xg = reinterpret_cast<const float4*>(x);
        #pragma unroll
        for (int it = 0; it < (TILE_R * DIMS / 4) / NTHREADS; ++it) {  // 8 iters
            int lin = it * NTHREADS + tid;   // 0..4095
            int r  = lin >> 5;               // row in tile
            int c4 = lin & 31;               // float4 column
            float4 v = make_float4(0.f, 0.f, 0.f, 0.f);
            if (row0 + r < n) v = xg[(size_t)(row0 + r) * 32 + c4];
            *reinterpret_cast<float4*>(&xs[r * XS_PITCH + c4 * 4]) = v;
        }
    }
    __syncthreads();

    // ---- sim GEMM: thread computes rows ty*4..+3, slots tx*4..+3 ----
    const float4* xs4  = reinterpret_cast<const float4*>(xs);   // pitch 33
    const float4* msT4 = reinterpret_cast<const float4*>(msT);  // pitch 17
    {
        ull acc[4][2];
        #pragma unroll
        for (int i = 0; i < 4; ++i) { acc[i][0] = 0ull; acc[i][1] = 0ull; }

        #pragma unroll 4
        for (int k4 = 0; k4 < DIMS / 4; ++k4) {
            float4 mv0 = msT4[(4 * k4 + 0) * (MST_PITCH/4) + tx];
            float4 mv1 = msT4[(4 * k4 + 1) * (MST_PITCH/4) + tx];
            float4 mv2 = msT4[(4 * k4 + 2) * (MST_PITCH/4) + tx];
            float4 mv3 = msT4[(4 * k4 + 3) * (MST_PITCH/4) + tx];
            ull m0a = pk2(mv0.x, mv0.y), m0b = pk2(mv0.z, mv0.w);
            ull m1a = pk2(mv1.x, mv1.y), m1b = pk2(mv1.z, mv1.w);
            ull m2a = pk2(mv2.x, mv2.y), m2b = pk2(mv2.z, mv2.w);
            ull m3a = pk2(mv3.x, mv3.y), m3b = pk2(mv3.z, mv3.w);
            #pragma unroll
            for (int i = 0; i < 4; ++i) {
                float4 xv = xs4[(ty * 4 + i) * (XS_PITCH/4) + k4];
                ull xb;
                xb = pk2(xv.x, xv.x);
                acc[i][0] = fma2(xb, m0a, acc[i][0]); acc[i][1] = fma2(xb, m0b, acc[i][1]);
                xb = pk2(xv.y, xv.y);
                acc[i][0] = fma2(xb, m1a, acc[i][0]); acc[i][1] = fma2(xb, m1b, acc[i][1]);
                xb = pk2(xv.z, xv.z);
                acc[i][0] = fma2(xb, m2a, acc[i][0]); acc[i][1] = fma2(xb, m2b, acc[i][1]);
                xb = pk2(xv.w, xv.w);
                acc[i][0] = fma2(xb, m3a, acc[i][0]); acc[i][1] = fma2(xb, m3b, acc[i][1]);
            }
        }
        // write sim tile to shared
        #pragma unroll
        for (int i = 0; i < 4; ++i) {
            float2 a0 = upk(acc[i][0]);
            float2 a1 = upk(acc[i][1]);
            int r = ty * 4 + i;
            float* sr = &sims[r * SIMS_PITCH + tx * 4];
            sr[0] = a0.x; sr[1] = a0.y; sr[2] = a1.x; sr[3] = a1.y;
        }
    }
    __syncthreads();

    // ---- softmax (warps 0-3) in parallel with gate dot (warps 4-7) ----
    if (tid < TILE_R) {
        // one row per thread; pitch 65 -> conflict-free across lanes
        float* srow = &sims[tid * SIMS_PITCH];
        float mx = srow[0];
        #pragma unroll
        for (int j = 1; j < MSLOTS; ++j) mx = fmaxf(mx, srow[j]);
        float sum = 0.f;
        #pragma unroll
        for (int j = 0; j < MSLOTS; ++j) {
            float e = __expf(srow[j] - mx);
            srow[j] = e;              // store unnormalized exp
            sum += e;
        }
        rinv[tid] = 1.0f / sum;       // fold normalization into epilogue
    } else if (tid < 2 * TILE_R) {
        int r = tid - TILE_R;
        const float4* xr  = reinterpret_cast<const float4*>(&xs[r * XS_PITCH]);
        const float4* gw4 = reinterpret_cast<const float4*>(gw);
        float t = 0.f;
        #pragma unroll
        for (int c = 0; c < DIMS / 4; ++c) {
            float4 a = xr[c], b = gw4[c];
            t += a.x * b.x + a.y * b.y + a.z * b.z + a.w * b.w;
        }
        t += gate_b[0];
        grow[r] = 1.0f / (1.0f + __expf(-t));
    }
    __syncthreads();

    // ---- read GEMM: rows ty*4..+3, dims {4tx..4tx+3} and {64+4tx..+3} ----
    const float4* ms4 = reinterpret_cast<const float4*>(ms);   // pitch 32
    ull racc[4][4];
    #pragma unroll
    for (int i = 0; i < 4; ++i)
        #pragma unroll
        for (int h = 0; h < 4; ++h) racc[i][h] = 0ull;

    #pragma unroll 4
    for (int k = 0; k < MSLOTS; ++k) {
        float4 mlo = ms4[k * 32 + tx];        // dims 4tx..4tx+3
        float4 mhi = ms4[k * 32 + 16 + tx];   // dims 64+4tx..
        ull b0 = pk2(mlo.x, mlo.y), b1 = pk2(mlo.z, mlo.w);
        ull b2 = pk2(mhi.x, mhi.y), b3 = pk2(mhi.z, mhi.w);
        #pragma unroll
        for (int i = 0; i < 4; ++i) {
            float a = sims[(ty * 4 + i) * SIMS_PITCH + k];
            ull ab = pk2(a, a);
            racc[i][0] = fma2(ab, b0, racc[i][0]);
            racc[i][1] = fma2(ab, b1, racc[i][1]);
            racc[i][2] = fma2(ab, b2, racc[i][2]);
            racc[i][3] = fma2(ab, b3, racc[i][3]);
        }
    }

    // ---- epilogue: out = g*read/Z + (1-g)*x ----
    float4* og = reinterpret_cast<float4*>(out);
    #pragma unroll
    for (int i = 0; i < 4; ++i) {
        int r = ty * 4 + i;
        if (row0 + r < n) {
            float g   = grow[r];
            float iz  = rinv[r];
            float gz  = g * iz;
            float omg = 1.0f - g;
            float2 r0 = upk(racc[i][0]), r1 = upk(racc[i][1]);
            float2 r2 = upk(racc[i][2]), r3 = upk(racc[i][3]);
            float4 xlo = xs4[r * (XS_PITCH/4) + tx];
            float4 xhi = xs4[r * (XS_PITCH/4) + 16 + tx];
            float4 o0, o1;
            o0.x = gz * r0.x + omg * xlo.x;
            o0.y = gz * r0.y + omg * xlo.y;
            o0.z = gz * r1.x + omg * xlo.z;
            o0.w = gz * r1.y + omg * xlo.w;
            o1.x = gz * r2.x + omg * xhi.x;
            o1.y = gz * r2.y + omg * xhi.y;
            o1.z = gz * r3.x + omg * xhi.z;
            o1.w = gz * r3.y + omg * xhi.w;
            og[(size_t)(row0 + r) * 32 + tx]      = o0;
            og[(size_t)(row0 + r) * 32 + 16 + tx] = o1;
        }
    }
}

extern "C" void kernel_launch(void* const* d_in, const int* in_sizes, int n_in,
                              void* d_out, int out_size)
{
    const float* x      = (const float*)d_in[0];
    const float* mem    = (const float*)d_in[1];
    const float* gate_w = (const float*)d_in[2];
    const float* gate_b = (const float*)d_in[3];
    float* out = (float*)d_out;

    int n = in_sizes[0] / DIMS;
    int grid = (n + TILE_R - 1) / TILE_R;
    size_t smem = SMEM_FLOATS * sizeof(float);

    cudaFuncSetAttribute(gated_memory_kernel,
                         cudaFuncAttributeMaxDynamicSharedMemorySize, (int)smem);
    gated_memory_kernel<<<grid, NTHREADS, smem>>>(x, mem, gate_w, gate_b, out, n);
}

// round 11
// speedup vs baseline: 1.9120x; 1.9120x over previous
#include <cuda_runtime.h>
#include <cuda_bf16.h>
#include <stdint.h>

#define DIMS     128
#define MSLOTS   64
#define TILE_R   256
#define NTH      256
#define NSM      148

// ---------------- SMEM layout (byte offsets) ----------------
// xh/xm: [256 rows][128 bf16], 256B pitch, 16B-unit xor swizzle (col16 ^= row&7)
#define XH      0u
#define XM      65536u
// B1 (GEMM1 B = mem row-major = col-major k128 x n72): [72 slots][272B pitch] bf16
#define B1Hoff  131072u
#define B1Moff  150656u
#define B1_PITCH 272
// B2 (GEMM2 B = memT: [128 dims][144B pitch], 64 slots contiguous) bf16
#define B2Hoff  170240u
#define B2Moff  188672u
#define B2_PITCH 144
#define SMEM_TOTAL 207104u

static __device__ __forceinline__ uint32_t smem_u32(const void* p) {
    uint32_t a;
    asm("{ .reg .u64 t; cvta.to.shared.u64 t, %1; cvt.u32.u64 %0, t; }" : "=r"(a) : "l"(p));
    return a;
}
static __device__ __forceinline__ void ldsm4(uint32_t* r, uint32_t a) {
    asm volatile("ldmatrix.sync.aligned.m8n8.x4.shared.b16 {%0,%1,%2,%3}, [%4];"
                 : "=r"(r[0]), "=r"(r[1]), "=r"(r[2]), "=r"(r[3]) : "r"(a));
}
static __device__ __forceinline__ void mma16816(float* d, const uint32_t* a,
                                                uint32_t b0, uint32_t b1) {
    asm volatile(
        "mma.sync.aligned.m16n8k16.row.col.f32.bf16.bf16.f32 "
        "{%0,%1,%2,%3}, {%4,%5,%6,%7}, {%8,%9}, {%0,%1,%2,%3};"
        : "+f"(d[0]), "+f"(d[1]), "+f"(d[2]), "+f"(d[3])
        : "r"(a[0]), "r"(a[1]), "r"(a[2]), "r"(a[3]), "r"(b0), "r"(b1));
}
static __device__ __forceinline__ uint32_t pk2bf(__nv_bfloat16 a, __nv_bfloat16 b) {
    __nv_bfloat162 t; t.x = a; t.y = b;
    return *reinterpret_cast<uint32_t*>(&t);
}
// split pair of floats into bf16 hi + bf16 mid packed words
static __device__ __forceinline__ void splitpk(float a, float b,
                                               uint32_t& hi, uint32_t& mid) {
    __nv_bfloat16 ha = __float2bfloat16_rn(a);
    __nv_bfloat16 hb = __float2bfloat16_rn(b);
    hi  = pk2bf(ha, hb);
    mid = pk2bf(__float2bfloat16_rn(a - __bfloat162float(ha)),
                __float2bfloat16_rn(b - __bfloat162float(hb)));
}
static __device__ __forceinline__ float2 ubf2(uint32_t v) {
    return __bfloat1622float2(*reinterpret_cast<__nv_bfloat162*>(&v));
}

__global__ void __launch_bounds__(NTH, 1)
gated_memory_mma(const float* __restrict__ x,
                 const float* __restrict__ mem,
                 const float* __restrict__ gate_w,
                 const float* __restrict__ gate_b,
                 float* __restrict__ out,
                 int n, int ntiles)
{
    extern __shared__ char smc[];
    const uint32_t sb = smem_u32(smc);
    const int tid  = threadIdx.x;
    const int lane = tid & 31;
    const int w    = tid >> 5;          // warp 0..7; rows w*32..w*32+31
    const int q    = lane & 3;          // thread-in-group
    const int gp   = lane >> 2;         // group id 0..7

    // ---- stage B operands (once per CTA, before first sync) ----
    for (int i = tid; i < MSLOTS * DIMS; i += NTH) {
        int s = i >> 7, d = i & 127;
        float v = mem[i];
        __nv_bfloat16 h = __float2bfloat16_rn(v);
        __nv_bfloat16 m = __float2bfloat16_rn(v - __bfloat162float(h));
        *(__nv_bfloat16*)(smc + B1Hoff + s * B1_PITCH + d * 2) = h;
        *(__nv_bfloat16*)(smc + B1Moff + s * B1_PITCH + d * 2) = m;
        *(__nv_bfloat16*)(smc + B2Hoff + d * B2_PITCH + s * 2) = h;
        *(__nv_bfloat16*)(smc + B2Moff + d * B2_PITCH + s * 2) = m;
    }
    if (tid < DIMS) {   // gate row = slot 64 of B1
        float v = gate_w[tid];
        __nv_bfloat16 h = __float2bfloat16_rn(v);
        __nv_bfloat16 m = __float2bfloat16_rn(v - __bfloat162float(h));
        *(__nv_bfloat16*)(smc + B1Hoff + 64 * B1_PITCH + tid * 2) = h;
        *(__nv_bfloat16*)(smc + B1Moff + 64 * B1_PITCH + tid * 2) = m;
    }
    // zero slots 65..71 of B1 (7 * 272B = 476 words)
    for (int i = tid; i < 476; i += NTH) {
        *(uint32_t*)(smc + B1Hoff + 65 * B1_PITCH + i * 4) = 0u;
        *(uint32_t*)(smc + B1Moff + 65 * B1_PITCH + i * 4) = 0u;
    }
    const float gbias = gate_b[0];

    const float4* xg = reinterpret_cast<const float4*>(x);

    for (int t = blockIdx.x; t < ntiles; t += gridDim.x) {
        const int row0 = t * TILE_R;

        // ---- stage x tile: split fp32 -> bf16 hi/mid, swizzled 16B stores ----
        #pragma unroll
        for (int it = 0; it < 16; ++it) {
            int lin = it * NTH + tid;
            int row = lin >> 4, c16 = lin & 15;
            float4 v0 = make_float4(0.f, 0.f, 0.f, 0.f), v1 = v0;
            int g = row0 + row;
            if (g < n) {
                v0 = xg[(size_t)g * 32 + c16 * 2];
                v1 = xg[(size_t)g * 32 + c16 * 2 + 1];
            }
            uint4 H, M;
            splitpk(v0.x, v0.y, H.x, M.x);
            splitpk(v0.z, v0.w, H.y, M.y);
            splitpk(v1.x, v1.y, H.z, M.z);
            splitpk(v1.z, v1.w, H.w, M.w);
            uint32_t off = row * 256 + ((c16 ^ (row & 7)) << 4);
            *reinterpret_cast<uint4*>(smc + XH + off) = H;
            *reinterpret_cast<uint4*>(smc + XM + off) = M;
        }
        __syncthreads();

        // ---- GEMM1: sim[32 x 72] per warp = x @ [mem|gw]^T, 3-pass split ----
        float acc[2][9][4];
        #pragma unroll
        for (int mt = 0; mt < 2; ++mt)
            #pragma unroll
            for (int nt = 0; nt < 9; ++nt)
                #pragma unroll
                for (int j = 0; j < 4; ++j) acc[mt][nt][j] = 0.f;

        const int lr = lane & 7, mi = lane >> 3;
        #pragma unroll
        for (int kt = 0; kt < 8; ++kt) {
            uint32_t ah[2][4], am[2][4];
            #pragma unroll
            for (int mt = 0; mt < 2; ++mt) {
                int row = w * 32 + mt * 16 + (mi & 1) * 8 + lr;
                int c16 = 2 * kt + (mi >> 1);
                uint32_t off = row * 256 + ((c16 ^ (row & 7)) << 4);
                ldsm4(ah[mt], sb + XH + off);
                ldsm4(am[mt], sb + XM + off);
            }
            #pragma unroll
            for (int nt = 0; nt < 9; ++nt) {
                uint32_t bo = B1Hoff + (nt * 8 + gp) * B1_PITCH + (kt * 16 + 2 * q) * 2;
                uint32_t bh0 = *(const uint32_t*)(smc + bo);
                uint32_t bh1 = *(const uint32_t*)(smc + bo + 16);
                uint32_t bm0 = *(const uint32_t*)(smc + bo + (B1Moff - B1Hoff));
                uint32_t bm1 = *(const uint32_t*)(smc + bo + (B1Moff - B1Hoff) + 16);
                #pragma unroll
                for (int mt = 0; mt < 2; ++mt) {
                    mma16816(acc[mt][nt], ah[mt], bh0, bh1);
                    mma16816(acc[mt][nt], ah[mt], bm0, bm1);
                    mma16816(acc[mt][nt], am[mt], bh0, bh1);
                }
            }
        }

        // ---- softmax + gate (register/quad-shuffle only) ----
        float gg[2][2], riv[2][2];
        #pragma unroll
        for (int mt = 0; mt < 2; ++mt) {
            #pragma unroll
            for (int rh = 0; rh < 2; ++rh) {
                float mx = acc[mt][0][rh * 2];
                #pragma unroll
                for (int nt = 0; nt < 8; ++nt) {
                    mx = fmaxf(mx, acc[mt][nt][rh * 2]);
                    mx = fmaxf(mx, acc[mt][nt][rh * 2 + 1]);
                }
                mx = fmaxf(mx, __shfl_xor_sync(0xffffffffu, mx, 1));
                mx = fmaxf(mx, __shfl_xor_sync(0xffffffffu, mx, 2));
                float s = 0.f;
                #pragma unroll
                for (int nt = 0; nt < 8; ++nt) {
                    float e0 = __expf(acc[mt][nt][rh * 2]     - mx);
                    float e1 = __expf(acc[mt][nt][rh * 2 + 1] - mx);
                    acc[mt][nt][rh * 2]     = e0;
                    acc[mt][nt][rh * 2 + 1] = e1;
                    s += e0 + e1;
                }
                s += __shfl_xor_sync(0xffffffffu, s, 1);
                s += __shfl_xor_sync(0xffffffffu, s, 2);
                riv[mt][rh] = 1.0f / s;
                float gv = acc[mt][8][rh * 2];            // sim col 64 lives at q==0
                gv = __shfl_sync(0xffffffffu, gv, lane & ~3);
                gg[mt][rh] = 1.0f / (1.0f + __expf(-(gv + gbias)));
            }
        }

        // ---- repack P accumulators into GEMM2 A fragments (hi/mid) ----
        uint32_t aPh[2][4][4], aPm[2][4][4];
        #pragma unroll
        for (int mt = 0; mt < 2; ++mt) {
            #pragma unroll
            for (int kt = 0; kt < 4; ++kt) {
                splitpk(acc[mt][2*kt][0],   acc[mt][2*kt][1],   aPh[mt][kt][0], aPm[mt][kt][0]);
                splitpk(acc[mt][2*kt][2],   acc[mt][2*kt][3],   aPh[mt][kt][1], aPm[mt][kt][1]);
                splitpk(acc[mt][2*kt+1][0], acc[mt][2*kt+1][1], aPh[mt][kt][2], aPm[mt][kt][2]);
                splitpk(acc[mt][2*kt+1][2], acc[mt][2*kt+1][3], aPh[mt][kt][3], aPm[mt][kt][3]);
            }
        }

        // ---- GEMM2 (read = P @ mem) in two 64-dim halves + fused epilogue ----
        #pragma unroll
        for (int half = 0; half < 2; ++half) {
            float acc2[2][8][4];
            #pragma unroll
            for (int mt = 0; mt < 2; ++mt)
                #pragma unroll
                for (int nt = 0; nt < 8; ++nt)
                    #pragma unroll
                    for (int j = 0; j < 4; ++j) acc2[mt][nt][j] = 0.f;

            #pragma unroll
            for (int kt = 0; kt < 4; ++kt) {
                #pragma unroll
                for (int nt = 0; nt < 8; ++nt) {
                    uint32_t bo = B2Hoff + (half * 64 + nt * 8 + gp) * B2_PITCH
                                + (kt * 16 + 2 * q) * 2;
                    uint32_t bh0 = *(const uint32_t*)(smc + bo);
                    uint32_t bh1 = *(const uint32_t*)(smc + bo + 16);
                    uint32_t bm0 = *(const uint32_t*)(smc + bo + (B2Moff - B2Hoff));
                    uint32_t bm1 = *(const uint32_t*)(smc + bo + (B2Moff - B2Hoff) + 16);
                    #pragma unroll
                    for (int mt = 0; mt < 2; ++mt) {
                        mma16816(acc2[mt][nt], aPh[mt][kt], bh0, bh1);
                        mma16816(acc2[mt][nt], aPh[mt][kt], bm0, bm1);
                        mma16816(acc2[mt][nt], aPm[mt][kt], bh0, bh1);
                    }
                }
            }

            // epilogue: out = x + g*(riv*read - x)
            #pragma unroll
            for (int mt = 0; mt < 2; ++mt) {
                #pragma unroll
                for (int rh = 0; rh < 2; ++rh) {
                    int row = w * 32 + mt * 16 + rh * 8 + gp;
                    int g = row0 + row;
                    if (g < n) {
                        const float G  = gg[mt][rh];
                        const float RI = riv[mt][rh];
                        #pragma unroll
                        for (int nt = 0; nt < 8; ++nt) {
                            int d0 = half * 64 + nt * 8 + 2 * q;
                            uint32_t xoff = row * 256 + (((d0 >> 3) ^ (row & 7)) << 4)
                                          + (d0 & 7) * 2;
                            float2 fh = ubf2(*(const uint32_t*)(smc + XH + xoff));
                            float2 fm = ubf2(*(const uint32_t*)(smc + XM + xoff));
                            float x0 = fh.x + fm.x, x1 = fh.y + fm.y;
                            float r0 = acc2[mt][nt][rh * 2]     * RI;
                            float r1 = acc2[mt][nt][rh * 2 + 1] * RI;
                            float2 o;
                            o.x = x0 + G * (r0 - x0);
                            o.y = x1 + G * (r1 - x1);
                            *reinterpret_cast<float2*>(out + (size_t)g * DIMS + d0) = o;
                        }
                    }
                }
            }
        }
        __syncthreads();   // xh/xm reused next tile
    }
}

extern "C" void kernel_launch(void* const* d_in, const int* in_sizes, int n_in,
                              void* d_out, int out_size)
{
    const float* x      = (const float*)d_in[0];
    const float* mem    = (const float*)d_in[1];
    const float* gate_w = (const float*)d_in[2];
    const float* gate_b = (const float*)d_in[3];
    float* out = (float*)d_out;

    int n = in_sizes[0] / DIMS;
    int ntiles = (n + TILE_R - 1) / TILE_R;

    cudaFuncSetAttribute(gated_memory_mma,
                         cudaFuncAttributeMaxDynamicSharedMemorySize, (int)SMEM_TOTAL);
    int grid = ntiles < NSM ? ntiles : NSM;
    gated_memory_mma<<<grid, NTH, SMEM_TOTAL>>>(x, mem, gate_w, gate_b, out, n, ntiles);
}

// round 12
// speedup vs baseline: 2.1930x; 1.1470x over previous
#include <cuda_runtime.h>
#include <cuda_bf16.h>
#include <stdint.h>

#define DIMS     128
#define MSLOTS   64
#define TILE_R   128
#define NTH      256
#define NSM      148

// ---------------- SMEM layout (byte offsets), per CTA ----------------
// xh/xm: [128 rows][128 bf16], 256B pitch, 16B-unit xor swizzle (col16 ^= row&7)
#define XH      0u
#define XM      32768u
// B1 (mem + gate row, k128 x n72): [72 slots][272B pitch] bf16
// pitch 272 = 17*16B (odd multiple of 16B -> conflict-free ldmatrix row gather)
#define B1Hoff  65536u
#define B1Moff  85120u
#define B1_PITCH 272
#define SMEM_TOTAL 104704u

static __device__ __forceinline__ uint32_t smem_u32(const void* p) {
    uint32_t a;
    asm("{ .reg .u64 t; cvta.to.shared.u64 t, %1; cvt.u32.u64 %0, t; }" : "=r"(a) : "l"(p));
    return a;
}
static __device__ __forceinline__ void ldsm4(uint32_t* r, uint32_t a) {
    asm volatile("ldmatrix.sync.aligned.m8n8.x4.shared.b16 {%0,%1,%2,%3}, [%4];"
                 : "=r"(r[0]), "=r"(r[1]), "=r"(r[2]), "=r"(r[3]) : "r"(a));
}
static __device__ __forceinline__ void ldsm4t(uint32_t* r, uint32_t a) {
    asm volatile("ldmatrix.sync.aligned.m8n8.x4.trans.shared.b16 {%0,%1,%2,%3}, [%4];"
                 : "=r"(r[0]), "=r"(r[1]), "=r"(r[2]), "=r"(r[3]) : "r"(a));
}
static __device__ __forceinline__ void mma16816(float* d, const uint32_t* a,
                                                uint32_t b0, uint32_t b1) {
    asm volatile(
        "mma.sync.aligned.m16n8k16.row.col.f32.bf16.bf16.f32 "
        "{%0,%1,%2,%3}, {%4,%5,%6,%7}, {%8,%9}, {%0,%1,%2,%3};"
        : "+f"(d[0]), "+f"(d[1]), "+f"(d[2]), "+f"(d[3])
        : "r"(a[0]), "r"(a[1]), "r"(a[2]), "r"(a[3]), "r"(b0), "r"(b1));
}
static __device__ __forceinline__ uint32_t pk2bf(__nv_bfloat16 a, __nv_bfloat16 b) {
    __nv_bfloat162 t; t.x = a; t.y = b;
    return *reinterpret_cast<uint32_t*>(&t);
}
static __device__ __forceinline__ void splitpk(float a, float b,
                                               uint32_t& hi, uint32_t& mid) {
    __nv_bfloat16 ha = __float2bfloat16_rn(a);
    __nv_bfloat16 hb = __float2bfloat16_rn(b);
    hi  = pk2bf(ha, hb);
    mid = pk2bf(__float2bfloat16_rn(a - __bfloat162float(ha)),
                __float2bfloat16_rn(b - __bfloat162float(hb)));
}
static __device__ __forceinline__ float2 ubf2(uint32_t v) {
    return __bfloat1622float2(*reinterpret_cast<__nv_bfloat162*>(&v));
}

__global__ void __launch_bounds__(NTH, 2)
gated_memory_mma(const float* __restrict__ x,
                 const float* __restrict__ mem,
                 const float* __restrict__ gate_w,
                 const float* __restrict__ gate_b,
                 float* __restrict__ out,
                 int n, int ntiles)
{
    extern __shared__ char smc[];
    const uint32_t sb = smem_u32(smc);
    const int tid  = threadIdx.x;
    const int lane = tid & 31;
    const int w    = tid >> 5;          // warp 0..7; rows w*16..w*16+15
    const int q    = lane & 3;
    const int gp   = lane >> 2;

    // ---- stage B1 (mem rows + gate row + zero pad), hi/mid split ----
    for (int i = tid; i < MSLOTS * DIMS; i += NTH) {
        int s = i >> 7, d = i & 127;
        float v = mem[i];
        __nv_bfloat16 h = __float2bfloat16_rn(v);
        __nv_bfloat16 m = __float2bfloat16_rn(v - __bfloat162float(h));
        *(__nv_bfloat16*)(smc + B1Hoff + s * B1_PITCH + d * 2) = h;
        *(__nv_bfloat16*)(smc + B1Moff + s * B1_PITCH + d * 2) = m;
    }
    if (tid < DIMS) {   // gate row = slot 64
        float v = gate_w[tid];
        __nv_bfloat16 h = __float2bfloat16_rn(v);
        __nv_bfloat16 m = __float2bfloat16_rn(v - __bfloat162float(h));
        *(__nv_bfloat16*)(smc + B1Hoff + 64 * B1_PITCH + tid * 2) = h;
        *(__nv_bfloat16*)(smc + B1Moff + 64 * B1_PITCH + tid * 2) = m;
    }
    for (int i = tid; i < 476; i += NTH) {   // zero slots 65..71
        *(uint32_t*)(smc + B1Hoff + 65 * B1_PITCH + i * 4) = 0u;
        *(uint32_t*)(smc + B1Moff + 65 * B1_PITCH + i * 4) = 0u;
    }
    const float gbias = gate_b[0];

    const float4* xg = reinterpret_cast<const float4*>(x);

    for (int t = blockIdx.x; t < ntiles; t += gridDim.x) {
        const int row0 = t * TILE_R;

        // ---- stage x tile: split fp32 -> bf16 hi/mid, swizzled 16B stores ----
        #pragma unroll
        for (int it = 0; it < 8; ++it) {
            int lin = it * NTH + tid;
            int row = lin >> 4, c16 = lin & 15;
            float4 v0 = make_float4(0.f, 0.f, 0.f, 0.f), v1 = v0;
            int g = row0 + row;
            if (g < n) {
                v0 = xg[(size_t)g * 32 + c16 * 2];
                v1 = xg[(size_t)g * 32 + c16 * 2 + 1];
            }
            uint4 H, M;
            splitpk(v0.x, v0.y, H.x, M.x);
            splitpk(v0.z, v0.w, H.y, M.y);
            splitpk(v1.x, v1.y, H.z, M.z);
            splitpk(v1.z, v1.w, H.w, M.w);
            uint32_t off = row * 256 + ((c16 ^ (row & 7)) << 4);
            *reinterpret_cast<uint4*>(smc + XH + off) = H;
            *reinterpret_cast<uint4*>(smc + XM + off) = M;
        }
        __syncthreads();

        // ---- GEMM1: sim[16 x 72] per warp = x @ [mem|gw]^T, 3-pass split ----
        float acc[9][4];
        #pragma unroll
        for (int nt = 0; nt < 9; ++nt)
            #pragma unroll
            for (int j = 0; j < 4; ++j) acc[nt][j] = 0.f;

        const int lr = lane & 7, mi = lane >> 3;
        #pragma unroll
        for (int kt = 0; kt < 8; ++kt) {
            uint32_t ah[4], am[4];
            {
                int row = w * 16 + (mi & 1) * 8 + lr;
                int c16 = 2 * kt + (mi >> 1);
                uint32_t off = row * 256 + ((c16 ^ (row & 7)) << 4);
                ldsm4(ah, sb + XH + off);
                ldsm4(am, sb + XM + off);
            }
            #pragma unroll
            for (int nt = 0; nt < 9; ++nt) {
                uint32_t bo = B1Hoff + (nt * 8 + gp) * B1_PITCH + (kt * 16 + 2 * q) * 2;
                uint32_t bh0 = *(const uint32_t*)(smc + bo);
                uint32_t bh1 = *(const uint32_t*)(smc + bo + 16);
                uint32_t bm0 = *(const uint32_t*)(smc + bo + (B1Moff - B1Hoff));
                uint32_t bm1 = *(const uint32_t*)(smc + bo + (B1Moff - B1Hoff) + 16);
                mma16816(acc[nt], ah, bh0, bh1);
                mma16816(acc[nt], ah, bm0, bm1);
                mma16816(acc[nt], am, bh0, bh1);
            }
        }

        // ---- softmax + gate (register/quad-shuffle only) ----
        float gg[2], riv[2];
        #pragma unroll
        for (int rh = 0; rh < 2; ++rh) {
            float mx = acc[0][rh * 2];
            #pragma unroll
            for (int nt = 0; nt < 8; ++nt) {
                mx = fmaxf(mx, acc[nt][rh * 2]);
                mx = fmaxf(mx, acc[nt][rh * 2 + 1]);
            }
            mx = fmaxf(mx, __shfl_xor_sync(0xffffffffu, mx, 1));
            mx = fmaxf(mx, __shfl_xor_sync(0xffffffffu, mx, 2));
            float s = 0.f;
            #pragma unroll
            for (int nt = 0; nt < 8; ++nt) {
                float e0 = __expf(acc[nt][rh * 2]     - mx);
                float e1 = __expf(acc[nt][rh * 2 + 1] - mx);
                acc[nt][rh * 2]     = e0;
                acc[nt][rh * 2 + 1] = e1;
                s += e0 + e1;
            }
            s += __shfl_xor_sync(0xffffffffu, s, 1);
            s += __shfl_xor_sync(0xffffffffu, s, 2);
            riv[rh] = 1.0f / s;
            float gv = acc[8][rh * 2];                 // sim col 64 (q==0 lane holds it)
            gv = __shfl_sync(0xffffffffu, gv, lane & ~3);
            gg[rh] = 1.0f / (1.0f + __expf(-(gv + gbias)));
        }

        // ---- repack P accumulators into GEMM2 A fragments (hi/mid) ----
        uint32_t aPh[4][4], aPm[4][4];
        #pragma unroll
        for (int kt = 0; kt < 4; ++kt) {
            splitpk(acc[2*kt][0],   acc[2*kt][1],   aPh[kt][0], aPm[kt][0]);
            splitpk(acc[2*kt][2],   acc[2*kt][3],   aPh[kt][1], aPm[kt][1]);
            splitpk(acc[2*kt+1][0], acc[2*kt+1][1], aPh[kt][2], aPm[kt][2]);
            splitpk(acc[2*kt+1][2], acc[2*kt+1][3], aPh[kt][3], aPm[kt][3]);
        }

        // ---- GEMM2 (read = P @ mem), B frags via ldmatrix.trans on B1 ----
        // trans-gather lane addressing (per x4 op covering k16 x n16):
        //   s = kt*16 + ((lane>>3)&1)*8 + (lane&7),  d = n0 + (lane>>4)*8
        const int sB = ((lane >> 3) & 1) * 8 + (lane & 7);
        const int dB = (lane >> 4) * 8;
        #pragma unroll
        for (int half = 0; half < 2; ++half) {
            float acc2[8][4];
            #pragma unroll
            for (int nt = 0; nt < 8; ++nt)
                #pragma unroll
                for (int j = 0; j < 4; ++j) acc2[nt][j] = 0.f;

            #pragma unroll
            for (int kt = 0; kt < 4; ++kt) {
                #pragma unroll
                for (int np = 0; np < 4; ++np) {
                    int n0 = half * 64 + np * 16;
                    uint32_t bo = (uint32_t)((kt * 16 + sB) * B1_PITCH + (n0 + dB) * 2);
                    uint32_t bh[4], bm[4];
                    ldsm4t(bh, sb + B1Hoff + bo);
                    ldsm4t(bm, sb + B1Moff + bo);
                    mma16816(acc2[np*2],   aPh[kt], bh[0], bh[1]);
                    mma16816(acc2[np*2],   aPh[kt], bm[0], bm[1]);
                    mma16816(acc2[np*2],   aPm[kt], bh[0], bh[1]);
                    mma16816(acc2[np*2+1], aPh[kt], bh[2], bh[3]);
                    mma16816(acc2[np*2+1], aPh[kt], bm[2], bm[3]);
                    mma16816(acc2[np*2+1], aPm[kt], bh[2], bh[3]);
                }
            }

            // epilogue: out = x + g*(riv*read - x)
            #pragma unroll
            for (int rh = 0; rh < 2; ++rh) {
                int row = w * 16 + rh * 8 + gp;
                int g = row0 + row;
                if (g < n) {
                    const float G  = gg[rh];
                    const float RI = riv[rh];
                    #pragma unroll
                    for (int nt = 0; nt < 8; ++nt) {
                        int d0 = half * 64 + nt * 8 + 2 * q;
                        uint32_t xoff = row * 256 + (((d0 >> 3) ^ (row & 7)) << 4)
                                      + (d0 & 7) * 2;
                        float2 fh = ubf2(*(const uint32_t*)(smc + XH + xoff));
                        float2 fm = ubf2(*(const uint32_t*)(smc + XM + xoff));
                        float x0 = fh.x + fm.x, x1 = fh.y + fm.y;
                        float r0 = acc2[nt][rh * 2]     * RI;
                        float r1 = acc2[nt][rh * 2 + 1] * RI;
                        float2 o;
                        o.x = x0 + G * (r0 - x0);
                        o.y = x1 + G * (r1 - x1);
                        *reinterpret_cast<float2*>(out + (size_t)g * DIMS + d0) = o;
                    }
                }
            }
        }
        __syncthreads();   // xh/xm reused next tile
    }
}

extern "C" void kernel_launch(void* const* d_in, const int* in_sizes, int n_in,
                              void* d_out, int out_size)
{
    const float* x      = (const float*)d_in[0];
    const float* mem    = (const float*)d_in[1];
    const float* gate_w = (const float*)d_in[2];
    const float* gate_b = (const float*)d_in[3];
    float* out = (float*)d_out;

    int n = in_sizes[0] / DIMS;
    int ntiles = (n + TILE_R - 1) / TILE_R;

    cudaFuncSetAttribute(gated_memory_mma,
                         cudaFuncAttributeMaxDynamicSharedMemorySize, (int)SMEM_TOTAL);
    int grid = ntiles < 2 * NSM ? ntiles : 2 * NSM;
    gated_memory_mma<<<grid, NTH, SMEM_TOTAL>>>(x, mem, gate_w, gate_b, out, n, ntiles);
}